// round 1
// baseline (speedup 1.0000x reference)
#include <cuda_runtime.h>

#define TPB 256

// ---------------------------------------------------------------------------
// Problem constants: B=2, C=96, D=H=W=64, WS=8, N=64 tokens, HEADS=3, HD=32
// 3 branches, 8192 windows per branch.
// ---------------------------------------------------------------------------

__device__ __forceinline__ int x_off(int br, int b, int c, int s, int p, int q) {
    // offset into (B, C, D, H, W) = (2, 96, 64, 64, 64), row-major
    int d, h, w;
    if (br == 0)      { d = s; h = p; w = q; }   // image=(b,d), spatial (h,w)
    else if (br == 1) { d = q; h = p; w = s; }   // image=(b,w), spatial (h,d)
    else              { d = p; h = s; w = q; }   // image=(b,h), spatial (d,w)
    return (((b * 96 + c) * 64 + d) * 64 + h) * 64 + w;
}

// Shared memory layout (float offsets)
//  xs   [64][97]   0      .. 6208    (window input; reused as attn output "os")
//  qkvs [64][289]  6208   .. 24704
//  wst  [96][97]   24704  .. 34016   (staged weight tile, wst[c][o])
//  as_  [64][65]   34016  .. 38176   (attention scores, one head at a time)
//  tb   [225]      38176  .. 38401   (rpb table slice for current head)
//  invs [96]       38401  .. 38497   (BN scale)
//  shs  [96]       38497  .. 38593   (BN shift)
//  idxs [4096]int  38593  .. 42689
#define SMEM_FLOATS 42689

template<bool ATOMIC>
__global__ __launch_bounds__(TPB)
void swin_win_kernel(
    const float* __restrict__ x,
    const float* __restrict__ qkv_w, const float* __restrict__ qkv_b,
    const float* __restrict__ proj_w, const float* __restrict__ proj_b,
    const float* __restrict__ rpb_table,
    const float* __restrict__ bn_g, const float* __restrict__ bn_b,
    const float* __restrict__ bn_m, const float* __restrict__ bn_v,
    const int* __restrict__ rpb_index,
    float* __restrict__ out, int br_base)
{
    extern __shared__ float sm[];
    float* xs   = sm;              // [64][97] ; later reused as attn-out "os"
    float* qkvs = sm + 6208;       // [64][289]
    float* wst  = sm + 24704;      // [96][97]
    float* as_  = sm + 34016;      // [64][65]
    float* tb   = sm + 38176;      // [225]
    float* invs = sm + 38401;      // [96]
    float* shs  = sm + 38497;      // [96]
    int*   idxs = (int*)(sm + 38593); // [4096]

    const int tid = threadIdx.x;
    const int bid = blockIdx.x;
    const int br  = br_base + (bid >> 13);  // 8192 windows per branch
    const int wid = bid & 8191;
    const int g   = wid & 127;              // image index INNER (L2 line sharing)
    const int win = wid >> 7;               // window within 64x64 image: 8x8
    const int wi  = win >> 3;
    const int wj  = win & 7;
    const int b   = g >> 6;
    const int s   = g & 63;                 // d / w / h depending on branch

    // --- BN affine precompute + rpb index staging ------------------------
    if (tid < 96) {
        float inv = bn_g[br * 96 + tid] * rsqrtf(bn_v[br * 96 + tid] + 1e-5f);
        invs[tid] = inv;
        shs[tid]  = bn_b[br * 96 + tid] - bn_m[br * 96 + tid] * inv;
    }
    for (int i = tid; i < 4096; i += TPB) idxs[i] = rpb_index[i];

    // --- load window: xs[tok][c] -----------------------------------------
    for (int i = tid; i < 6144; i += TPB) {
        int c   = i >> 6;
        int tok = i & 63;
        int ti  = tok >> 3, tj = tok & 7;
        int p = wi * 8 + ti, q = wj * 8 + tj;
        xs[tok * 97 + c] = x[x_off(br, b, c, s, p, q)];
    }
    __syncthreads();

    const int tn = tid >> 4;   // token group 0..15 (4 tokens each)
    const int to = tid & 15;   // out-chan group 0..15 (6 outs each)

    // --- qkv = xs @ Wqkv^T + b, three 96-wide passes (q, k, v) -----------
    for (int pass = 0; pass < 3; ++pass) {
        const int obase = pass * 96;
        for (int i = tid; i < 9216; i += TPB) {
            int o = i / 96, c = i - o * 96;
            wst[c * 97 + o] = qkv_w[(br * 288 + obase + o) * 96 + c];
        }
        __syncthreads();

        float acc[4][6];
        #pragma unroll
        for (int j = 0; j < 6; ++j) {
            float bb = qkv_b[br * 288 + obase + to * 6 + j];
            #pragma unroll
            for (int i = 0; i < 4; ++i) acc[i][j] = bb;
        }
        for (int c = 0; c < 96; ++c) {
            float av[4], wv[6];
            #pragma unroll
            for (int i = 0; i < 4; ++i) av[i] = xs[(tn * 4 + i) * 97 + c];
            #pragma unroll
            for (int j = 0; j < 6; ++j) wv[j] = wst[c * 97 + to * 6 + j];
            #pragma unroll
            for (int i = 0; i < 4; ++i)
                #pragma unroll
                for (int j = 0; j < 6; ++j) acc[i][j] += av[i] * wv[j];
        }
        #pragma unroll
        for (int i = 0; i < 4; ++i)
            #pragma unroll
            for (int j = 0; j < 6; ++j)
                qkvs[(tn * 4 + i) * 289 + obase + to * 6 + j] = acc[i][j];
        __syncthreads();
    }

    // --- attention, one head at a time -----------------------------------
    for (int h = 0; h < 3; ++h) {
        if (tid < 225) tb[tid] = rpb_table[(br * 225 + tid) * 3 + h];
        __syncthreads();

        // scores: s[n][m] = scale * <q_n, k_m> + bias
        {
            const int ng = tid & 15;   // n = ng*4 + i
            const int mg = tid >> 4;   // m = mg*4 + k
            float sacc[4][4];
            #pragma unroll
            for (int i = 0; i < 4; ++i)
                #pragma unroll
                for (int k = 0; k < 4; ++k) sacc[i][k] = 0.f;
            for (int d = 0; d < 32; ++d) {
                float qv[4], kv[4];
                #pragma unroll
                for (int i = 0; i < 4; ++i)
                    qv[i] = qkvs[(ng * 4 + i) * 289 + h * 32 + d];
                #pragma unroll
                for (int k = 0; k < 4; ++k)
                    kv[k] = qkvs[(mg * 4 + k) * 289 + 96 + h * 32 + d];
                #pragma unroll
                for (int i = 0; i < 4; ++i)
                    #pragma unroll
                    for (int k = 0; k < 4; ++k) sacc[i][k] += qv[i] * kv[k];
            }
            #pragma unroll
            for (int i = 0; i < 4; ++i) {
                int n = ng * 4 + i;
                #pragma unroll
                for (int k = 0; k < 4; ++k) {
                    int m = mg * 4 + k;
                    as_[n * 65 + m] =
                        sacc[i][k] * 0.17677669529663687f + tb[idxs[n * 64 + m]];
                }
            }
        }
        __syncthreads();

        // row softmax
        if (tid < 64) {
            float mx = -1e30f;
            for (int m = 0; m < 64; ++m) mx = fmaxf(mx, as_[tid * 65 + m]);
            float sum = 0.f;
            for (int m = 0; m < 64; ++m) {
                float e = __expf(as_[tid * 65 + m] - mx);
                as_[tid * 65 + m] = e;
                sum += e;
            }
            float r = 1.f / sum;
            for (int m = 0; m < 64; ++m) as_[tid * 65 + m] *= r;
        }
        __syncthreads();

        // out = attn @ v  -> os[n][h*32 + d]   (os aliases xs, now dead)
        {
            const int ng = tid & 31;   // n = ng*2 + i
            const int dg = tid >> 5;   // d = dg*4 + jj
            float oacc[2][4];
            #pragma unroll
            for (int i = 0; i < 2; ++i)
                #pragma unroll
                for (int jj = 0; jj < 4; ++jj) oacc[i][jj] = 0.f;
            for (int m = 0; m < 64; ++m) {
                float av[2], vv[4];
                av[0] = as_[(ng * 2 + 0) * 65 + m];
                av[1] = as_[(ng * 2 + 1) * 65 + m];
                #pragma unroll
                for (int jj = 0; jj < 4; ++jj)
                    vv[jj] = qkvs[m * 289 + 192 + h * 32 + dg * 4 + jj];
                #pragma unroll
                for (int i = 0; i < 2; ++i)
                    #pragma unroll
                    for (int jj = 0; jj < 4; ++jj) oacc[i][jj] += av[i] * vv[jj];
            }
            #pragma unroll
            for (int i = 0; i < 2; ++i)
                #pragma unroll
                for (int jj = 0; jj < 4; ++jj)
                    xs[(ng * 2 + i) * 97 + h * 32 + dg * 4 + jj] = oacc[i][jj];
        }
        __syncthreads();
    }

    // --- proj + BN + LeakyReLU + store -----------------------------------
    for (int i = tid; i < 9216; i += TPB) {
        int co = i / 96, ci = i - co * 96;
        wst[ci * 97 + co] = proj_w[(br * 96 + co) * 96 + ci];
    }
    __syncthreads();

    {
        float acc[4][6];
        #pragma unroll
        for (int j = 0; j < 6; ++j) {
            float bb = proj_b[br * 96 + to * 6 + j];
            #pragma unroll
            for (int i = 0; i < 4; ++i) acc[i][j] = bb;
        }
        for (int ci = 0; ci < 96; ++ci) {
            float av[4], wv[6];
            #pragma unroll
            for (int i = 0; i < 4; ++i) av[i] = xs[(tn * 4 + i) * 97 + ci];
            #pragma unroll
            for (int j = 0; j < 6; ++j) wv[j] = wst[ci * 97 + to * 6 + j];
            #pragma unroll
            for (int i = 0; i < 4; ++i)
                #pragma unroll
                for (int j = 0; j < 6; ++j) acc[i][j] += av[i] * wv[j];
        }
        #pragma unroll
        for (int i = 0; i < 4; ++i) {
            int n  = tn * 4 + i;
            int ti = n >> 3, tj = n & 7;
            int p = wi * 8 + ti, q = wj * 8 + tj;
            #pragma unroll
            for (int j = 0; j < 6; ++j) {
                int co = to * 6 + j;
                float yn = acc[i][j] * invs[co] + shs[co];
                yn = (yn >= 0.f) ? yn : 0.01f * yn;
                int off = x_off(br, b, co, s, p, q);
                if (ATOMIC) atomicAdd(&out[off], yn);
                else        out[off] = yn;
            }
        }
    }
}

extern "C" void kernel_launch(void* const* d_in, const int* in_sizes, int n_in,
                              void* d_out, int out_size)
{
    (void)in_sizes; (void)n_in; (void)out_size;
    const float* x         = (const float*)d_in[0];
    const float* qkv_w     = (const float*)d_in[1];
    const float* qkv_b     = (const float*)d_in[2];
    const float* proj_w    = (const float*)d_in[3];
    const float* proj_b    = (const float*)d_in[4];
    const float* rpb_table = (const float*)d_in[5];
    const float* bn_g      = (const float*)d_in[6];
    const float* bn_b      = (const float*)d_in[7];
    const float* bn_m      = (const float*)d_in[8];
    const float* bn_v      = (const float*)d_in[9];
    const int*   rpb_index = (const int*)d_in[10];
    float* out = (float*)d_out;

    const int smem = SMEM_FLOATS * 4;
    cudaFuncSetAttribute(swin_win_kernel<false>,
                         cudaFuncAttributeMaxDynamicSharedMemorySize, smem);
    cudaFuncSetAttribute(swin_win_kernel<true>,
                         cudaFuncAttributeMaxDynamicSharedMemorySize, smem);

    // Branch 0: plain stores (covers every output element -> kills poison)
    swin_win_kernel<false><<<8192, TPB, smem>>>(
        x, qkv_w, qkv_b, proj_w, proj_b, rpb_table,
        bn_g, bn_b, bn_m, bn_v, rpb_index, out, 0);
    // Branches 1 & 2: accumulate
    swin_win_kernel<true><<<16384, TPB, smem>>>(
        x, qkv_w, qkv_b, proj_w, proj_b, rpb_table,
        bn_g, bn_b, bn_m, bn_v, rpb_index, out, 1);
}